// round 2
// baseline (speedup 1.0000x reference)
#include <cuda_runtime.h>

#define TEN 8      // nodes per CTA (node kernel)
#define TEE 16     // edges per CTA (edge kernel)
#define NODES_MAX 50000

typedef unsigned long long ull;

__device__ float g_agg_s[(size_t)NODES_MAX * 64];
__device__ float g_agg_v[(size_t)NODES_MAX * 192];

__device__ __forceinline__ ull ffma2(ull a, ull b, ull c) {
  ull d;
  asm("fma.rn.f32x2 %0, %1, %2, %3;" : "=l"(d) : "l"(a), "l"(b), "l"(c));
  return d;
}
__device__ __forceinline__ ull pack2(float x) {
  ull d;
  asm("mov.b64 %0, {%1, %1};" : "=l"(d) : "f"(x));
  return d;
}
__device__ __forceinline__ void upk8(const ull* a, float* f) {
#pragma unroll
  for (int j = 0; j < 4; j++) {
    f[2 * j]     = __int_as_float((int)(unsigned)(a[j] & 0xffffffffull));
    f[2 * j + 1] = __int_as_float((int)(unsigned)(a[j] >> 32));
  }
}
__device__ __forceinline__ void upk16(const ull* a, float* f) {
#pragma unroll
  for (int j = 0; j < 8; j++) {
    f[2 * j]     = __int_as_float((int)(unsigned)(a[j] & 0xffffffffull));
    f[2 * j + 1] = __int_as_float((int)(unsigned)(a[j] >> 32));
  }
}
__device__ __forceinline__ float sigm(float x) { return 1.0f / (1.0f + __expf(-x)); }

#define RSQRT3 0.5773502692f
#define INV1   0.0622573010f   // 1/sqrt(258)
#define INV2   0.0883883476f   // 1/sqrt(128)
#define INV0   0.0625f         // 1/sqrt(256)
#define INVU   0.0883883476f   // 1/sqrt(128)

// 8 edges (TE=8): accumulate row[0..7] * w2 into A[0..3]
#define ACC4(arrRow, w2, A) do {                                               \
    ulonglong2 _r0 = *reinterpret_cast<const ulonglong2*>(arrRow);             \
    ulonglong2 _r1 = *reinterpret_cast<const ulonglong2*>((arrRow) + 4);       \
    (A)[0] = ffma2(_r0.x, (w2), (A)[0]);                                       \
    (A)[1] = ffma2(_r0.y, (w2), (A)[1]);                                       \
    (A)[2] = ffma2(_r1.x, (w2), (A)[2]);                                       \
    (A)[3] = ffma2(_r1.y, (w2), (A)[3]);                                       \
  } while (0)

// 16 edges (TEE=16): accumulate row[0..15] * w2 into A[0..7]
#define ACC8(arrRow, w2, A) do {                                               \
    ulonglong2 _r0 = *reinterpret_cast<const ulonglong2*>(arrRow);             \
    ulonglong2 _r1 = *reinterpret_cast<const ulonglong2*>((arrRow) + 4);       \
    ulonglong2 _r2 = *reinterpret_cast<const ulonglong2*>((arrRow) + 8);       \
    ulonglong2 _r3 = *reinterpret_cast<const ulonglong2*>((arrRow) + 12);      \
    (A)[0] = ffma2(_r0.x, (w2), (A)[0]);                                       \
    (A)[1] = ffma2(_r0.y, (w2), (A)[1]);                                       \
    (A)[2] = ffma2(_r1.x, (w2), (A)[2]);                                       \
    (A)[3] = ffma2(_r1.y, (w2), (A)[3]);                                       \
    (A)[4] = ffma2(_r2.x, (w2), (A)[4]);                                       \
    (A)[5] = ffma2(_r2.y, (w2), (A)[5]);                                       \
    (A)[6] = ffma2(_r3.x, (w2), (A)[6]);                                       \
    (A)[7] = ffma2(_r3.y, (w2), (A)[7]);                                       \
  } while (0)

__global__ void zero_kernel(int N) {
  size_t i = (size_t)blockIdx.x * blockDim.x + threadIdx.x;
  size_t stride = (size_t)gridDim.x * blockDim.x;
  float4 z = make_float4(0.f, 0.f, 0.f, 0.f);
  size_t n_s = (size_t)N * 64 / 4;
  for (size_t t = i; t < n_s; t += stride) reinterpret_cast<float4*>(g_agg_s)[t] = z;
  size_t n_v = (size_t)N * 192 / 4;
  for (size_t t = i; t < n_v; t += stride) reinterpret_cast<float4*>(g_agg_v)[t] = z;
}

// ---------------------------------------------------------------------------
// Edge kernel: 16 edges per CTA, 128 threads, dynamic smem (82.5 KB).
// fused gather -> gated TP m1 -> gated TP m2 -> atomic aggregate
// ---------------------------------------------------------------------------

// smem layout offsets (in floats); all rows are TEE=16 floats = 64B aligned
#define OFF_XSR  0        // [130][16] raw xs
#define OFF_XSA  2080     // [130][16] xs * a_s
#define OFF_D1   4160     // [128][16]
#define OFF_XVA  6208     // [128][3][16]
#define OFF_MSR  12352    // [64][16]
#define OFF_MSA  13376
#define OFF_G    14400
#define OFF_D2   15424
#define OFF_MVA  16448    // [64][3][16]
#define OFF_P    19520    // [64][16]
#define OFF_ASX  20544    // [16]
#define OFF_AVX  20560    // [3][16]
#define OFF_SND  20608    // int [16]
#define OFF_RCV  20624    // int [16]
#define EDGE_SMEM_FLOATS 20640
#define EDGE_SMEM_BYTES (EDGE_SMEM_FLOATS * 4)

__global__ void __launch_bounds__(128) edge_kernel(
    const float* __restrict__ node_s, const float* __restrict__ node_v,
    const float* __restrict__ eas, const float* __restrict__ eav,
    const float* __restrict__ add_feat,
    const float* __restrict__ Wss1, const float* __restrict__ Wvs1,
    const float* __restrict__ Wsv1, const float* __restrict__ Wvv1,
    const float* __restrict__ b1,
    const float* __restrict__ Wss2, const float* __restrict__ Wvs2,
    const float* __restrict__ Wsv2, const float* __restrict__ Wvv2,
    const float* __restrict__ b2,
    const int* __restrict__ senders, const int* __restrict__ receivers,
    int E)
{
  extern __shared__ __align__(16) float sm[];
  float* xs_r = sm + OFF_XSR;   // [k][e] stride 16
  float* xs_a = sm + OFF_XSA;
  float* d1   = sm + OFF_D1;
  float* xva  = sm + OFF_XVA;   // [(v*3+c)][e]
  float* ms_r = sm + OFF_MSR;
  float* ms_a = sm + OFF_MSA;
  float* gT   = sm + OFF_G;
  float* d2   = sm + OFF_D2;
  float* mva  = sm + OFF_MVA;
  float* pT   = sm + OFF_P;
  float* asx  = sm + OFF_ASX;
  float* avx  = sm + OFF_AVX;   // [c][e] stride 16
  int*   sndx = (int*)(sm + OFF_SND);
  int*   rcvx = (int*)(sm + OFF_RCV);

  const int tid = threadIdx.x;
  const int e0 = blockIdx.x * TEE;

  if (tid < TEE) {
    int ge = e0 + tid;
    bool val = ge < E;
    sndx[tid] = val ? senders[ge] : 0;
    rcvx[tid] = val ? receivers[ge] : -1;
    asx[tid]  = val ? eas[ge] : 0.f;
#pragma unroll
    for (int i = 0; i < 3; i++) avx[i * 16 + tid] = val ? eav[ge * 3 + i] : 0.f;
  }
  __syncthreads();

  // gather xs = [node_s[snd] | node_s[rcv] | add_feat]
  for (int idx = tid; idx < TEE * 130; idx += 128) {
    int e = idx / 130, s = idx - e * 130;
    int r = rcvx[e] < 0 ? 0 : rcvx[e];
    float v;
    if (s < 64)       v = __ldg(node_s + (size_t)sndx[e] * 64 + s);
    else if (s < 128) v = __ldg(node_s + (size_t)r * 64 + (s - 64));
    else {
      int ge = e0 + e;
      v = (ge < E) ? __ldg(add_feat + (size_t)ge * 2 + (s - 128)) : 0.f;
    }
    xs_r[s * 16 + e] = v;
    xs_a[s * 16 + e] = v * asx[e];
  }
  // gather xv raw
  for (int idx = tid; idx < TEE * 384; idx += 128) {
    int e = idx / 384, j = idx - e * 384;
    int r = rcvx[e] < 0 ? 0 : rcvx[e];
    float v = (j < 192) ? __ldg(node_v + (size_t)sndx[e] * 192 + j)
                        : __ldg(node_v + (size_t)r * 192 + (j - 192));
    xva[j * 16 + e] = v;
  }
  __syncthreads();

  // d1 = (xv . av)/sqrt3 ; xva = xv * a_s
  for (int t = tid; t < TEE * 128; t += 128) {
    int v = t >> 4, e = t & 15;
    float r0 = xva[(v * 3 + 0) * 16 + e], r1 = xva[(v * 3 + 1) * 16 + e],
          r2 = xva[(v * 3 + 2) * 16 + e];
    d1[v * 16 + e] = (r0 * avx[e] + r1 * avx[16 + e] + r2 * avx[32 + e]) * RSQRT3;
    float a = asx[e];
    xva[(v * 3 + 0) * 16 + e] = r0 * a;
    xva[(v * 3 + 1) * 16 + e] = r1 * a;
    xva[(v * 3 + 2) * 16 + e] = r2 * a;
  }
  __syncthreads();

  // ---- m1 scalar: s1[o] = (xs*a_s)@Wss1 + d1@Wvs1 ----
  {
    const int o = tid;
    ull acc[8] = {0, 0, 0, 0, 0, 0, 0, 0};
#pragma unroll 2
    for (int k = 0; k < 130; k++) {
      ull w2 = pack2(__ldg(Wss1 + k * 128 + o));
      ACC8(xs_a + k * 16, w2, acc);
    }
#pragma unroll 4
    for (int k = 0; k < 128; k++) {
      ull w2 = pack2(__ldg(Wvs1 + k * 128 + o));
      ACC8(d1 + k * 16, w2, acc);
    }
    float sv[16]; upk16(acc, sv);
    float bo = __ldg(b1 + o);
    if (o < 64) {
#pragma unroll
      for (int e = 0; e < TEE; e++) {
        float s1 = sv[e] * INV1 + bo;
        float m = s1 * sigm(s1);
        ms_r[o * 16 + e] = m;
        ms_a[o * 16 + e] = m * asx[e];
      }
    } else {
#pragma unroll
      for (int e = 0; e < TEE; e++) {
        gT[(o - 64) * 16 + e] = sigm(sv[e] * INV1 + bo);
      }
    }
  }
  __syncthreads();

  // ---- m1 vector ----
  {
    const int o = tid & 63;
    ull accA[8] = {0, 0, 0, 0, 0, 0, 0, 0}, accB[8] = {0, 0, 0, 0, 0, 0, 0, 0};
    if (tid < 64) {          // comps 0,1 of q = (xv*a_s)@Wvv1
#pragma unroll 2
      for (int k = 0; k < 128; k++) {
        ull w2 = pack2(__ldg(Wvv1 + k * 64 + o));
        ACC8(xva + (k * 3 + 0) * 16, w2, accA);
        ACC8(xva + (k * 3 + 1) * 16, w2, accB);
      }
    } else {                 // comp 2 of q, plus p = xs@Wsv1
#pragma unroll 2
      for (int k = 0; k < 128; k++) {
        ull w2 = pack2(__ldg(Wvv1 + k * 64 + o));
        ACC8(xva + (k * 3 + 2) * 16, w2, accA);
      }
#pragma unroll 2
      for (int k = 0; k < 130; k++) {
        ull w2 = pack2(__ldg(Wsv1 + k * 64 + o));
        ACC8(xs_r + k * 16, w2, accB);
      }
      float pf[16]; upk16(accB, pf);
#pragma unroll
      for (int e = 0; e < TEE; e++) pT[o * 16 + e] = pf[e];
    }
    __syncthreads();
    float qa[16], qb[16];
    upk16(accA, qa); upk16(accB, qb);
    if (tid < 64) {
#pragma unroll
      for (int e = 0; e < TEE; e++) {
        float gi = gT[o * 16 + e] * INV1;
        float p = pT[o * 16 + e];
        mva[(o * 3 + 0) * 16 + e] = (qa[e] + p * avx[e]) * gi;
        mva[(o * 3 + 1) * 16 + e] = (qb[e] + p * avx[16 + e]) * gi;
      }
    } else {
#pragma unroll
      for (int e = 0; e < TEE; e++) {
        float gi = gT[o * 16 + e] * INV1;
        mva[(o * 3 + 2) * 16 + e] = (qa[e] + qb[e] * avx[32 + e]) * gi;
      }
    }
  }
  __syncthreads();

  // d2 = (mv . av)/sqrt3 ; mva = mv * a_s
  for (int t = tid; t < TEE * 64; t += 128) {
    int v = t >> 4, e = t & 15;
    float r0 = mva[(v * 3 + 0) * 16 + e], r1 = mva[(v * 3 + 1) * 16 + e],
          r2 = mva[(v * 3 + 2) * 16 + e];
    d2[v * 16 + e] = (r0 * avx[e] + r1 * avx[16 + e] + r2 * avx[32 + e]) * RSQRT3;
    float a = asx[e];
    mva[(v * 3 + 0) * 16 + e] = r0 * a;
    mva[(v * 3 + 1) * 16 + e] = r1 * a;
    mva[(v * 3 + 2) * 16 + e] = r2 * a;
  }
  __syncthreads();

  // ---- m2 scalar (+ atomic scatter of silu part) ----
  {
    const int o = tid;
    ull acc[8] = {0, 0, 0, 0, 0, 0, 0, 0};
#pragma unroll 4
    for (int k = 0; k < 64; k++) {
      ull w2 = pack2(__ldg(Wss2 + k * 128 + o));
      ACC8(ms_a + k * 16, w2, acc);
    }
#pragma unroll 4
    for (int k = 0; k < 64; k++) {
      ull w2 = pack2(__ldg(Wvs2 + k * 128 + o));
      ACC8(d2 + k * 16, w2, acc);
    }
    float sv[16]; upk16(acc, sv);
    float bo = __ldg(b2 + o);
    if (o < 64) {
#pragma unroll
      for (int e = 0; e < TEE; e++) {
        float s2 = sv[e] * INV2 + bo;
        float m = s2 * sigm(s2);
        int r = rcvx[e];
        if (r >= 0) atomicAdd(g_agg_s + (size_t)r * 64 + o, m);
      }
    } else {
#pragma unroll
      for (int e = 0; e < TEE; e++) {
        gT[(o - 64) * 16 + e] = sigm(sv[e] * INV2 + bo);
      }
    }
  }
  __syncthreads();

  // ---- m2 vector (+ atomic scatter) ----
  {
    const int o = tid & 63;
    ull accA[8] = {0, 0, 0, 0, 0, 0, 0, 0}, accB[8] = {0, 0, 0, 0, 0, 0, 0, 0};
    if (tid < 64) {
#pragma unroll 2
      for (int k = 0; k < 64; k++) {
        ull w2 = pack2(__ldg(Wvv2 + k * 64 + o));
        ACC8(mva + (k * 3 + 0) * 16, w2, accA);
        ACC8(mva + (k * 3 + 1) * 16, w2, accB);
      }
    } else {
#pragma unroll 2
      for (int k = 0; k < 64; k++) {
        ull w2 = pack2(__ldg(Wvv2 + k * 64 + o));
        ACC8(mva + (k * 3 + 2) * 16, w2, accA);
      }
#pragma unroll 2
      for (int k = 0; k < 64; k++) {
        ull w2 = pack2(__ldg(Wsv2 + k * 64 + o));
        ACC8(ms_r + k * 16, w2, accB);
      }
      float pf[16]; upk16(accB, pf);
#pragma unroll
      for (int e = 0; e < TEE; e++) pT[o * 16 + e] = pf[e];
    }
    __syncthreads();
    float qa[16], qb[16];
    upk16(accA, qa); upk16(accB, qb);
    if (tid < 64) {
#pragma unroll
      for (int e = 0; e < TEE; e++) {
        int r = rcvx[e];
        if (r < 0) continue;
        float gi = gT[o * 16 + e] * INV2;
        float p = pT[o * 16 + e];
        atomicAdd(g_agg_v + (size_t)r * 192 + o * 3 + 0, (qa[e] + p * avx[e]) * gi);
        atomicAdd(g_agg_v + (size_t)r * 192 + o * 3 + 1, (qb[e] + p * avx[16 + e]) * gi);
      }
    } else {
#pragma unroll
      for (int e = 0; e < TEE; e++) {
        int r = rcvx[e];
        if (r < 0) continue;
        float gi = gT[o * 16 + e] * INV2;
        atomicAdd(g_agg_v + (size_t)r * 192 + o * 3 + 2, (qa[e] + qb[e] * avx[32 + e]) * gi);
      }
    }
  }
}

// ---------------------------------------------------------------------------
// Node kernel: fused [node | agg] -> gated TP u0 -> TP u1 -> residual + out
// (TEN = 8 nodes per CTA, static smem)
// ---------------------------------------------------------------------------
__global__ void __launch_bounds__(128) node_kernel(
    const float* __restrict__ node_s, const float* __restrict__ node_v,
    const float* __restrict__ nas, const float* __restrict__ nav,
    const float* __restrict__ Wss0, const float* __restrict__ Wvs0,
    const float* __restrict__ Wsv0, const float* __restrict__ Wvv0,
    const float* __restrict__ b0,
    const float* __restrict__ Wssu, const float* __restrict__ Wvsu,
    const float* __restrict__ Wsvu, const float* __restrict__ Wvvu,
    const float* __restrict__ bu,
    float* __restrict__ out, int N)
{
  __shared__ __align__(16) float xs_rT[128][TEN];
  __shared__ __align__(16) float xs_aT[128][TEN];
  __shared__ __align__(16) float d1T[128][TEN];
  __shared__ __align__(16) float xvaT[128][3][TEN];
  __shared__ __align__(16) float hs_rT[64][TEN];
  __shared__ __align__(16) float hs_aT[64][TEN];
  __shared__ __align__(16) float gT[64][TEN];
  __shared__ __align__(16) float d2T[64][TEN];
  __shared__ __align__(16) float hvaT[64][3][TEN];
  __shared__ __align__(16) float pT[64][TEN];
  __shared__ float asx[TEN], avx[3][TEN];

  const int tid = threadIdx.x;
  const int n0 = blockIdx.x * TEN;

  if (tid < TEN) {
    int n = n0 + tid;
    bool val = n < N;
    asx[tid] = val ? nas[n] : 0.f;
#pragma unroll
    for (int i = 0; i < 3; i++) avx[i][tid] = val ? nav[n * 3 + i] : 0.f;
  }
  __syncthreads();

  for (int idx = tid; idx < TEN * 128; idx += 128) {
    int e = idx >> 7, s = idx & 127;
    int n = n0 + e; if (n >= N) n = 0;
    float v = (s < 64) ? __ldg(node_s + (size_t)n * 64 + s)
                       : g_agg_s[(size_t)n * 64 + (s - 64)];
    xs_rT[s][e] = v;
    xs_aT[s][e] = v * asx[e];
  }
  for (int idx = tid; idx < TEN * 384; idx += 128) {
    int e = idx / 384, j = idx - e * 384;
    int n = n0 + e; if (n >= N) n = 0;
    float v = (j < 192) ? __ldg(node_v + (size_t)n * 192 + j)
                        : g_agg_v[(size_t)n * 192 + (j - 192)];
    xvaT[j / 3][j % 3][e] = v;
  }
  __syncthreads();

  for (int t = tid; t < TEN * 128; t += 128) {
    int v = t >> 3, e = t & 7;
    float r0 = xvaT[v][0][e], r1 = xvaT[v][1][e], r2 = xvaT[v][2][e];
    d1T[v][e] = (r0 * avx[0][e] + r1 * avx[1][e] + r2 * avx[2][e]) * RSQRT3;
    float a = asx[e];
    xvaT[v][0][e] = r0 * a; xvaT[v][1][e] = r1 * a; xvaT[v][2][e] = r2 * a;
  }
  __syncthreads();

  // ---- u0 scalar ----
  {
    const int o = tid;
    ull acc[4] = {0, 0, 0, 0};
#pragma unroll 4
    for (int k = 0; k < 128; k++) {
      ull w2 = pack2(__ldg(Wss0 + k * 128 + o));
      ACC4(xs_aT[k], w2, acc);
    }
#pragma unroll 4
    for (int k = 0; k < 128; k++) {
      ull w2 = pack2(__ldg(Wvs0 + k * 128 + o));
      ACC4(d1T[k], w2, acc);
    }
    float sv[8]; upk8(acc, sv);
    float bo = __ldg(b0 + o);
    if (o < 64) {
#pragma unroll
      for (int e = 0; e < TEN; e++) {
        float s1 = sv[e] * INV0 + bo;
        float m = s1 * sigm(s1);
        hs_rT[o][e] = m;
        hs_aT[o][e] = m * asx[e];
      }
    } else {
#pragma unroll
      for (int e = 0; e < TEN; e++) {
        gT[o - 64][e] = sigm(sv[e] * INV0 + bo);
      }
    }
  }
  __syncthreads();

  // ---- u0 vector ----
  {
    const int o = tid & 63;
    ull accA[4] = {0, 0, 0, 0}, accB[4] = {0, 0, 0, 0};
    if (tid < 64) {
#pragma unroll 2
      for (int k = 0; k < 128; k++) {
        ull w2 = pack2(__ldg(Wvv0 + k * 64 + o));
        ACC4(xvaT[k][0], w2, accA);
        ACC4(xvaT[k][1], w2, accB);
      }
    } else {
#pragma unroll 4
      for (int k = 0; k < 128; k++) {
        ull w2 = pack2(__ldg(Wvv0 + k * 64 + o));
        ACC4(xvaT[k][2], w2, accA);
      }
#pragma unroll 4
      for (int k = 0; k < 128; k++) {
        ull w2 = pack2(__ldg(Wsv0 + k * 64 + o));
        ACC4(xs_rT[k], w2, accB);
      }
      float pf[8]; upk8(accB, pf);
#pragma unroll
      for (int e = 0; e < TEN; e++) pT[o][e] = pf[e];
    }
    __syncthreads();
    float qa[8], qb[8];
    upk8(accA, qa); upk8(accB, qb);
    if (tid < 64) {
#pragma unroll
      for (int e = 0; e < TEN; e++) {
        float gi = gT[o][e] * INV0;
        float p = pT[o][e];
        hvaT[o][0][e] = (qa[e] + p * avx[0][e]) * gi;
        hvaT[o][1][e] = (qb[e] + p * avx[1][e]) * gi;
      }
    } else {
#pragma unroll
      for (int e = 0; e < TEN; e++) {
        float gi = gT[o][e] * INV0;
        hvaT[o][2][e] = (qa[e] + qb[e] * avx[2][e]) * gi;
      }
    }
  }
  __syncthreads();

  for (int t = tid; t < TEN * 64; t += 128) {
    int v = t >> 3, e = t & 7;
    float r0 = hvaT[v][0][e], r1 = hvaT[v][1][e], r2 = hvaT[v][2][e];
    d2T[v][e] = (r0 * avx[0][e] + r1 * avx[1][e] + r2 * avx[2][e]) * RSQRT3;
    float a = asx[e];
    hvaT[v][0][e] = r0 * a; hvaT[v][1][e] = r1 * a; hvaT[v][2][e] = r2 * a;
  }
  __syncthreads();

  // ---- u1 scalar + residual ----
  if (tid < 64) {
    const int o = tid;
    ull acc[4] = {0, 0, 0, 0};
#pragma unroll 4
    for (int k = 0; k < 64; k++) {
      ull w2 = pack2(__ldg(Wssu + k * 64 + o));
      ACC4(hs_aT[k], w2, acc);
    }
#pragma unroll 4
    for (int k = 0; k < 64; k++) {
      ull w2 = pack2(__ldg(Wvsu + k * 64 + o));
      ACC4(d2T[k], w2, acc);
    }
    float sv[8]; upk8(acc, sv);
    float bo = __ldg(bu + o);
#pragma unroll
    for (int e = 0; e < TEN; e++) {
      int n = n0 + e;
      if (n < N)
        out[(size_t)n * 256 + o] =
            __ldg(node_s + (size_t)n * 64 + o) + sv[e] * INVU + bo;
    }
  }

  // ---- u1 vector + residual ----
  {
    const int o = tid & 63;
    ull accA[4] = {0, 0, 0, 0}, accB[4] = {0, 0, 0, 0};
    if (tid < 64) {
#pragma unroll 2
      for (int k = 0; k < 64; k++) {
        ull w2 = pack2(__ldg(Wvvu + k * 64 + o));
        ACC4(hvaT[k][0], w2, accA);
        ACC4(hvaT[k][1], w2, accB);
      }
    } else {
#pragma unroll 4
      for (int k = 0; k < 64; k++) {
        ull w2 = pack2(__ldg(Wvvu + k * 64 + o));
        ACC4(hvaT[k][2], w2, accA);
      }
#pragma unroll 4
      for (int k = 0; k < 64; k++) {
        ull w2 = pack2(__ldg(Wsvu + k * 64 + o));
        ACC4(hs_rT[k], w2, accB);
      }
      float pf[8]; upk8(accB, pf);
#pragma unroll
      for (int e = 0; e < TEN; e++) pT[o][e] = pf[e];
    }
    __syncthreads();
    float qa[8], qb[8];
    upk8(accA, qa); upk8(accB, qb);
    if (tid < 64) {
#pragma unroll
      for (int e = 0; e < TEN; e++) {
        int n = n0 + e;
        if (n >= N) continue;
        float p = pT[o][e];
        out[(size_t)n * 256 + 64 + o * 3 + 0] =
            __ldg(node_v + (size_t)n * 192 + o * 3 + 0) + (qa[e] + p * avx[0][e]) * INVU;
        out[(size_t)n * 256 + 64 + o * 3 + 1] =
            __ldg(node_v + (size_t)n * 192 + o * 3 + 1) + (qb[e] + p * avx[1][e]) * INVU;
      }
    } else {
#pragma unroll
      for (int e = 0; e < TEN; e++) {
        int n = n0 + e;
        if (n >= N) continue;
        out[(size_t)n * 256 + 64 + o * 3 + 2] =
            __ldg(node_v + (size_t)n * 192 + o * 3 + 2) + (qa[e] + qb[e] * avx[2][e]) * INVU;
      }
    }
  }
}

extern "C" void kernel_launch(void* const* d_in, const int* in_sizes, int n_in,
                              void* d_out, int out_size) {
  const float* node_s = (const float*)d_in[0];
  const float* node_v = (const float*)d_in[1];
  const float* nas    = (const float*)d_in[2];
  const float* nav    = (const float*)d_in[3];
  const float* eas    = (const float*)d_in[4];
  const float* eav    = (const float*)d_in[5];
  const float* add_f  = (const float*)d_in[6];
  const float* m1Wss  = (const float*)d_in[7];
  const float* m1Wvs  = (const float*)d_in[8];
  const float* m1Wsv  = (const float*)d_in[9];
  const float* m1Wvv  = (const float*)d_in[10];
  const float* m1b    = (const float*)d_in[11];
  const float* m2Wss  = (const float*)d_in[12];
  const float* m2Wvs  = (const float*)d_in[13];
  const float* m2Wsv  = (const float*)d_in[14];
  const float* m2Wvv  = (const float*)d_in[15];
  const float* m2b    = (const float*)d_in[16];
  const float* u0Wss  = (const float*)d_in[17];
  const float* u0Wvs  = (const float*)d_in[18];
  const float* u0Wsv  = (const float*)d_in[19];
  const float* u0Wvv  = (const float*)d_in[20];
  const float* u0b    = (const float*)d_in[21];
  const float* u1Wss  = (const float*)d_in[22];
  const float* u1Wvs  = (const float*)d_in[23];
  const float* u1Wsv  = (const float*)d_in[24];
  const float* u1Wvv  = (const float*)d_in[25];
  const float* u1b    = (const float*)d_in[26];
  const int* senders   = (const int*)d_in[27];
  const int* receivers = (const int*)d_in[28];

  int E = in_sizes[27];
  int N = in_sizes[0] / 64;

  cudaFuncSetAttribute(edge_kernel, cudaFuncAttributeMaxDynamicSharedMemorySize,
                       EDGE_SMEM_BYTES);

  zero_kernel<<<512, 256>>>(N);
  edge_kernel<<<(E + TEE - 1) / TEE, 128, EDGE_SMEM_BYTES>>>(
      node_s, node_v, eas, eav, add_f,
      m1Wss, m1Wvs, m1Wsv, m1Wvv, m1b,
      m2Wss, m2Wvs, m2Wsv, m2Wvv, m2b,
      senders, receivers, E);
  node_kernel<<<(N + TEN - 1) / TEN, 128>>>(
      node_s, node_v, nas, nav,
      u0Wss, u0Wvs, u0Wsv, u0Wvv, u0b,
      u1Wss, u1Wvs, u1Wsv, u1Wvv, u1b,
      (float*)d_out, N);
}

// round 3
// speedup vs baseline: 2.2207x; 2.2207x over previous
#include <cuda_runtime.h>

#define TE 8
#define NODES_MAX 50000

typedef unsigned long long ull;

__device__ float g_agg_s[(size_t)NODES_MAX * 64];
__device__ float g_agg_v[(size_t)NODES_MAX * 192];

__device__ __forceinline__ ull ffma2(ull a, ull b, ull c) {
  ull d;
  asm("fma.rn.f32x2 %0, %1, %2, %3;" : "=l"(d) : "l"(a), "l"(b), "l"(c));
  return d;
}
__device__ __forceinline__ ull pack2(float x) {
  ull d;
  asm("mov.b64 %0, {%1, %1};" : "=l"(d) : "f"(x));
  return d;
}
__device__ __forceinline__ void upk8(const ull* a, float* f) {
#pragma unroll
  for (int j = 0; j < 4; j++) {
    f[2 * j]     = __int_as_float((int)(unsigned)(a[j] & 0xffffffffull));
    f[2 * j + 1] = __int_as_float((int)(unsigned)(a[j] >> 32));
  }
}
__device__ __forceinline__ float sigm(float x) { return 1.0f / (1.0f + __expf(-x)); }

#define RSQRT3 0.5773502692f
#define INV1   0.0622573010f   // 1/sqrt(258)
#define INV2   0.0883883476f   // 1/sqrt(128)
#define INV0   0.0625f         // 1/sqrt(256)
#define INVU   0.0883883476f   // 1/sqrt(128)

// accumulate 8 packed-pair lanes: A[j] += row[2j..2j+1] * w2
#define ACC4(arrRow, w2, A) do {                                               \
    ulonglong2 _r0 = *reinterpret_cast<const ulonglong2*>(arrRow);             \
    ulonglong2 _r1 = *reinterpret_cast<const ulonglong2*>((arrRow) + 4);       \
    (A)[0] = ffma2(_r0.x, (w2), (A)[0]);                                       \
    (A)[1] = ffma2(_r0.y, (w2), (A)[1]);                                       \
    (A)[2] = ffma2(_r1.x, (w2), (A)[2]);                                       \
    (A)[3] = ffma2(_r1.y, (w2), (A)[3]);                                       \
  } while (0)

// K steps of o-th column of W (ld LDW), data rows at row + k*RS, 8 edges.
// Weight loads batched 8 deep (MLP=8); outer loop kept rolled for I-cache.
template <int K, int LDW, int RS>
__device__ __forceinline__ void gemmK(const float* __restrict__ W, int o,
                                      const float* __restrict__ row, ull* acc) {
#pragma unroll 1
  for (int k0 = 0; k0 < K; k0 += 8) {
    float w[8];
#pragma unroll
    for (int j = 0; j < 8; j++) w[j] = __ldg(W + (size_t)(k0 + j) * LDW + o);
#pragma unroll
    for (int j = 0; j < 8; j++) {
      ull w2 = pack2(w[j]);
      ACC4(row + (size_t)(k0 + j) * RS, w2, acc);
    }
  }
}

// Dual-row variant: same weight feeds two data rows (vector comps 0 and 1).
template <int K, int LDW, int RS>
__device__ __forceinline__ void gemmK2(const float* __restrict__ W, int o,
                                       const float* __restrict__ row0,
                                       const float* __restrict__ row1,
                                       ull* accA, ull* accB) {
#pragma unroll 1
  for (int k0 = 0; k0 < K; k0 += 8) {
    float w[8];
#pragma unroll
    for (int j = 0; j < 8; j++) w[j] = __ldg(W + (size_t)(k0 + j) * LDW + o);
#pragma unroll
    for (int j = 0; j < 8; j++) {
      ull w2 = pack2(w[j]);
      ACC4(row0 + (size_t)(k0 + j) * RS, w2, accA);
      ACC4(row1 + (size_t)(k0 + j) * RS, w2, accB);
    }
  }
}

__global__ void zero_kernel(int N) {
  size_t i = (size_t)blockIdx.x * blockDim.x + threadIdx.x;
  size_t stride = (size_t)gridDim.x * blockDim.x;
  float4 z = make_float4(0.f, 0.f, 0.f, 0.f);
  size_t n_s = (size_t)N * 64 / 4;
  for (size_t t = i; t < n_s; t += stride) reinterpret_cast<float4*>(g_agg_s)[t] = z;
  size_t n_v = (size_t)N * 192 / 4;
  for (size_t t = i; t < n_v; t += stride) reinterpret_cast<float4*>(g_agg_v)[t] = z;
}

// ---------------------------------------------------------------------------
// Edge kernel: 8 edges/CTA, 128 threads, 5 CTAs/SM.
// ---------------------------------------------------------------------------
__global__ void __launch_bounds__(128, 5) edge_kernel(
    const float* __restrict__ node_s, const float* __restrict__ node_v,
    const float* __restrict__ eas, const float* __restrict__ eav,
    const float* __restrict__ add_feat,
    const float* __restrict__ Wss1, const float* __restrict__ Wvs1,
    const float* __restrict__ Wsv1, const float* __restrict__ Wvv1,
    const float* __restrict__ b1,
    const float* __restrict__ Wss2, const float* __restrict__ Wvs2,
    const float* __restrict__ Wsv2, const float* __restrict__ Wvv2,
    const float* __restrict__ b2,
    const int* __restrict__ senders, const int* __restrict__ receivers,
    int E)
{
  __shared__ __align__(16) float xs_rT[130][TE];
  __shared__ __align__(16) float xs_aT[130][TE];
  __shared__ __align__(16) float d1T[128][TE];
  __shared__ __align__(16) float xvaT[128][3][TE];
  __shared__ __align__(16) float ms_rT[64][TE];
  __shared__ __align__(16) float ms_aT[64][TE];
  __shared__ __align__(16) float gT[64][TE];
  __shared__ __align__(16) float d2T[64][TE];
  __shared__ __align__(16) float mvaT[64][3][TE];
  __shared__ __align__(16) float pT[64][TE];
  __shared__ float asx[TE];
  __shared__ float avx[3][TE];
  __shared__ int sndx[TE], rcvx[TE];

  const int tid = threadIdx.x;
  const int e0 = blockIdx.x * TE;

  if (tid < TE) {
    int ge = e0 + tid;
    bool val = ge < E;
    sndx[tid] = val ? senders[ge] : 0;
    rcvx[tid] = val ? receivers[ge] : -1;
    asx[tid]  = val ? eas[ge] : 0.f;
#pragma unroll
    for (int i = 0; i < 3; i++) avx[i][tid] = val ? eav[ge * 3 + i] : 0.f;
  }
  __syncthreads();

  // gather xs = [node_s[snd] | node_s[rcv] | add_feat]
  for (int idx = tid; idx < TE * 130; idx += 128) {
    int e = idx / 130, s = idx - e * 130;
    int r = rcvx[e] < 0 ? 0 : rcvx[e];
    float v;
    if (s < 64)       v = __ldg(node_s + (size_t)sndx[e] * 64 + s);
    else if (s < 128) v = __ldg(node_s + (size_t)r * 64 + (s - 64));
    else {
      int ge = e0 + e;
      v = (ge < E) ? __ldg(add_feat + (size_t)ge * 2 + (s - 128)) : 0.f;
    }
    xs_rT[s][e] = v;
    xs_aT[s][e] = v * asx[e];
  }
  // gather xv raw
  for (int idx = tid; idx < TE * 384; idx += 128) {
    int e = idx / 384, j = idx - e * 384;
    int r = rcvx[e] < 0 ? 0 : rcvx[e];
    float v = (j < 192) ? __ldg(node_v + (size_t)sndx[e] * 192 + j)
                        : __ldg(node_v + (size_t)r * 192 + (j - 192));
    xvaT[j / 3][j % 3][e] = v;
  }
  __syncthreads();

  // d1 = (xv . av)/sqrt3 ; xva = xv * a_s
  for (int t = tid; t < TE * 128; t += 128) {
    int v = t >> 3, e = t & 7;
    float r0 = xvaT[v][0][e], r1 = xvaT[v][1][e], r2 = xvaT[v][2][e];
    d1T[v][e] = (r0 * avx[0][e] + r1 * avx[1][e] + r2 * avx[2][e]) * RSQRT3;
    float a = asx[e];
    xvaT[v][0][e] = r0 * a; xvaT[v][1][e] = r1 * a; xvaT[v][2][e] = r2 * a;
  }
  __syncthreads();

  // ---- m1 scalar: s1[o] = (xs*a_s)@Wss1 + d1@Wvs1 ----
  {
    const int o = tid;
    ull acc[4] = {0, 0, 0, 0};
    gemmK<128, 128, TE>(Wss1, o, &xs_aT[0][0], acc);
    {  // remainder k = 128, 129
      float w0 = __ldg(Wss1 + (size_t)128 * 128 + o);
      float w1 = __ldg(Wss1 + (size_t)129 * 128 + o);
      ACC4(&xs_aT[128][0], pack2(w0), acc);
      ACC4(&xs_aT[129][0], pack2(w1), acc);
    }
    gemmK<128, 128, TE>(Wvs1, o, &d1T[0][0], acc);
    float sv[8]; upk8(acc, sv);
    float bo = __ldg(b1 + o);
    if (o < 64) {
#pragma unroll
      for (int e = 0; e < TE; e++) {
        float s1 = sv[e] * INV1 + bo;
        float m = s1 * sigm(s1);
        ms_rT[o][e] = m;
        ms_aT[o][e] = m * asx[e];
      }
    } else {
#pragma unroll
      for (int e = 0; e < TE; e++) {
        gT[o - 64][e] = sigm(sv[e] * INV1 + bo);
      }
    }
  }
  __syncthreads();

  // ---- m1 vector ----
  {
    const int o = tid & 63;
    ull accA[4] = {0, 0, 0, 0}, accB[4] = {0, 0, 0, 0};
    if (tid < 64) {
      gemmK2<128, 64, 3 * TE>(Wvv1, o, &xvaT[0][0][0], &xvaT[0][1][0], accA, accB);
    } else {
      gemmK<128, 64, 3 * TE>(Wvv1, o, &xvaT[0][2][0], accA);
      gemmK<128, 64, TE>(Wsv1, o, &xs_rT[0][0], accB);
      {  // remainder k = 128, 129
        float w0 = __ldg(Wsv1 + (size_t)128 * 64 + o);
        float w1 = __ldg(Wsv1 + (size_t)129 * 64 + o);
        ACC4(&xs_rT[128][0], pack2(w0), accB);
        ACC4(&xs_rT[129][0], pack2(w1), accB);
      }
      float pf[8]; upk8(accB, pf);
#pragma unroll
      for (int e = 0; e < TE; e++) pT[o][e] = pf[e];
    }
    __syncthreads();
    float qa[8], qb[8];
    upk8(accA, qa); upk8(accB, qb);
    if (tid < 64) {
#pragma unroll
      for (int e = 0; e < TE; e++) {
        float gi = gT[o][e] * INV1;
        float p = pT[o][e];
        mvaT[o][0][e] = (qa[e] + p * avx[0][e]) * gi;
        mvaT[o][1][e] = (qb[e] + p * avx[1][e]) * gi;
      }
    } else {
#pragma unroll
      for (int e = 0; e < TE; e++) {
        float gi = gT[o][e] * INV1;
        mvaT[o][2][e] = (qa[e] + qb[e] * avx[2][e]) * gi;
      }
    }
  }
  __syncthreads();

  // d2 = (mv . av)/sqrt3 ; mva = mv * a_s
  for (int t = tid; t < TE * 64; t += 128) {
    int v = t >> 3, e = t & 7;
    float r0 = mvaT[v][0][e], r1 = mvaT[v][1][e], r2 = mvaT[v][2][e];
    d2T[v][e] = (r0 * avx[0][e] + r1 * avx[1][e] + r2 * avx[2][e]) * RSQRT3;
    float a = asx[e];
    mvaT[v][0][e] = r0 * a; mvaT[v][1][e] = r1 * a; mvaT[v][2][e] = r2 * a;
  }
  __syncthreads();

  // ---- m2 scalar (+ atomic scatter of silu part) ----
  {
    const int o = tid;
    ull acc[4] = {0, 0, 0, 0};
    gemmK<64, 128, TE>(Wss2, o, &ms_aT[0][0], acc);
    gemmK<64, 128, TE>(Wvs2, o, &d2T[0][0], acc);
    float sv[8]; upk8(acc, sv);
    float bo = __ldg(b2 + o);
    if (o < 64) {
#pragma unroll
      for (int e = 0; e < TE; e++) {
        float s2 = sv[e] * INV2 + bo;
        float m = s2 * sigm(s2);
        int r = rcvx[e];
        if (r >= 0) atomicAdd(g_agg_s + (size_t)r * 64 + o, m);
      }
    } else {
#pragma unroll
      for (int e = 0; e < TE; e++) {
        gT[o - 64][e] = sigm(sv[e] * INV2 + bo);
      }
    }
  }
  __syncthreads();

  // ---- m2 vector (+ atomic scatter) ----
  {
    const int o = tid & 63;
    ull accA[4] = {0, 0, 0, 0}, accB[4] = {0, 0, 0, 0};
    if (tid < 64) {
      gemmK2<64, 64, 3 * TE>(Wvv2, o, &mvaT[0][0][0], &mvaT[0][1][0], accA, accB);
    } else {
      gemmK<64, 64, 3 * TE>(Wvv2, o, &mvaT[0][2][0], accA);
      gemmK<64, 64, TE>(Wsv2, o, &ms_rT[0][0], accB);
      float pf[8]; upk8(accB, pf);
#pragma unroll
      for (int e = 0; e < TE; e++) pT[o][e] = pf[e];
    }
    __syncthreads();
    float qa[8], qb[8];
    upk8(accA, qa); upk8(accB, qb);
    if (tid < 64) {
#pragma unroll
      for (int e = 0; e < TE; e++) {
        int r = rcvx[e];
        if (r < 0) continue;
        float gi = gT[o][e] * INV2;
        float p = pT[o][e];
        atomicAdd(g_agg_v + (size_t)r * 192 + o * 3 + 0, (qa[e] + p * avx[0][e]) * gi);
        atomicAdd(g_agg_v + (size_t)r * 192 + o * 3 + 1, (qb[e] + p * avx[1][e]) * gi);
      }
    } else {
#pragma unroll
      for (int e = 0; e < TE; e++) {
        int r = rcvx[e];
        if (r < 0) continue;
        float gi = gT[o][e] * INV2;
        atomicAdd(g_agg_v + (size_t)r * 192 + o * 3 + 2, (qa[e] + qb[e] * avx[2][e]) * gi);
      }
    }
  }
}

// ---------------------------------------------------------------------------
// Node kernel: fused [node | agg] -> gated TP u0 -> TP u1 -> residual + out
// ---------------------------------------------------------------------------
__global__ void __launch_bounds__(128, 5) node_kernel(
    const float* __restrict__ node_s, const float* __restrict__ node_v,
    const float* __restrict__ nas, const float* __restrict__ nav,
    const float* __restrict__ Wss0, const float* __restrict__ Wvs0,
    const float* __restrict__ Wsv0, const float* __restrict__ Wvv0,
    const float* __restrict__ b0,
    const float* __restrict__ Wssu, const float* __restrict__ Wvsu,
    const float* __restrict__ Wsvu, const float* __restrict__ Wvvu,
    const float* __restrict__ bu,
    float* __restrict__ out, int N)
{
  __shared__ __align__(16) float xs_rT[128][TE];
  __shared__ __align__(16) float xs_aT[128][TE];
  __shared__ __align__(16) float d1T[128][TE];
  __shared__ __align__(16) float xvaT[128][3][TE];
  __shared__ __align__(16) float hs_rT[64][TE];
  __shared__ __align__(16) float hs_aT[64][TE];
  __shared__ __align__(16) float gT[64][TE];
  __shared__ __align__(16) float d2T[64][TE];
  __shared__ __align__(16) float hvaT[64][3][TE];
  __shared__ __align__(16) float pT[64][TE];
  __shared__ float asx[TE], avx[3][TE];

  const int tid = threadIdx.x;
  const int n0 = blockIdx.x * TE;

  if (tid < TE) {
    int n = n0 + tid;
    bool val = n < N;
    asx[tid] = val ? nas[n] : 0.f;
#pragma unroll
    for (int i = 0; i < 3; i++) avx[i][tid] = val ? nav[n * 3 + i] : 0.f;
  }
  __syncthreads();

  for (int idx = tid; idx < TE * 128; idx += 128) {
    int e = idx >> 7, s = idx & 127;
    int n = n0 + e; if (n >= N) n = 0;
    float v = (s < 64) ? __ldg(node_s + (size_t)n * 64 + s)
                       : g_agg_s[(size_t)n * 64 + (s - 64)];
    xs_rT[s][e] = v;
    xs_aT[s][e] = v * asx[e];
  }
  for (int idx = tid; idx < TE * 384; idx += 128) {
    int e = idx / 384, j = idx - e * 384;
    int n = n0 + e; if (n >= N) n = 0;
    float v = (j < 192) ? __ldg(node_v + (size_t)n * 192 + j)
                        : g_agg_v[(size_t)n * 192 + (j - 192)];
    xvaT[j / 3][j % 3][e] = v;
  }
  __syncthreads();

  for (int t = tid; t < TE * 128; t += 128) {
    int v = t >> 3, e = t & 7;
    float r0 = xvaT[v][0][e], r1 = xvaT[v][1][e], r2 = xvaT[v][2][e];
    d1T[v][e] = (r0 * avx[0][e] + r1 * avx[1][e] + r2 * avx[2][e]) * RSQRT3;
    float a = asx[e];
    xvaT[v][0][e] = r0 * a; xvaT[v][1][e] = r1 * a; xvaT[v][2][e] = r2 * a;
  }
  __syncthreads();

  // ---- u0 scalar ----
  {
    const int o = tid;
    ull acc[4] = {0, 0, 0, 0};
    gemmK<128, 128, TE>(Wss0, o, &xs_aT[0][0], acc);
    gemmK<128, 128, TE>(Wvs0, o, &d1T[0][0], acc);
    float sv[8]; upk8(acc, sv);
    float bo = __ldg(b0 + o);
    if (o < 64) {
#pragma unroll
      for (int e = 0; e < TE; e++) {
        float s1 = sv[e] * INV0 + bo;
        float m = s1 * sigm(s1);
        hs_rT[o][e] = m;
        hs_aT[o][e] = m * asx[e];
      }
    } else {
#pragma unroll
      for (int e = 0; e < TE; e++) {
        gT[o - 64][e] = sigm(sv[e] * INV0 + bo);
      }
    }
  }
  __syncthreads();

  // ---- u0 vector ----
  {
    const int o = tid & 63;
    ull accA[4] = {0, 0, 0, 0}, accB[4] = {0, 0, 0, 0};
    if (tid < 64) {
      gemmK2<128, 64, 3 * TE>(Wvv0, o, &xvaT[0][0][0], &xvaT[0][1][0], accA, accB);
    } else {
      gemmK<128, 64, 3 * TE>(Wvv0, o, &xvaT[0][2][0], accA);
      gemmK<128, 64, TE>(Wsv0, o, &xs_rT[0][0], accB);
      float pf[8]; upk8(accB, pf);
#pragma unroll
      for (int e = 0; e < TE; e++) pT[o][e] = pf[e];
    }
    __syncthreads();
    float qa[8], qb[8];
    upk8(accA, qa); upk8(accB, qb);
    if (tid < 64) {
#pragma unroll
      for (int e = 0; e < TE; e++) {
        float gi = gT[o][e] * INV0;
        float p = pT[o][e];
        hvaT[o][0][e] = (qa[e] + p * avx[0][e]) * gi;
        hvaT[o][1][e] = (qb[e] + p * avx[1][e]) * gi;
      }
    } else {
#pragma unroll
      for (int e = 0; e < TE; e++) {
        float gi = gT[o][e] * INV0;
        hvaT[o][2][e] = (qa[e] + qb[e] * avx[2][e]) * gi;
      }
    }
  }
  __syncthreads();

  for (int t = tid; t < TE * 64; t += 128) {
    int v = t >> 3, e = t & 7;
    float r0 = hvaT[v][0][e], r1 = hvaT[v][1][e], r2 = hvaT[v][2][e];
    d2T[v][e] = (r0 * avx[0][e] + r1 * avx[1][e] + r2 * avx[2][e]) * RSQRT3;
    float a = asx[e];
    hvaT[v][0][e] = r0 * a; hvaT[v][1][e] = r1 * a; hvaT[v][2][e] = r2 * a;
  }
  __syncthreads();

  // ---- u1 scalar + residual ----
  if (tid < 64) {
    const int o = tid;
    ull acc[4] = {0, 0, 0, 0};
    gemmK<64, 64, TE>(Wssu, o, &hs_aT[0][0], acc);
    gemmK<64, 64, TE>(Wvsu, o, &d2T[0][0], acc);
    float sv[8]; upk8(acc, sv);
    float bo = __ldg(bu + o);
#pragma unroll
    for (int e = 0; e < TE; e++) {
      int n = n0 + e;
      if (n < N)
        out[(size_t)n * 256 + o] =
            __ldg(node_s + (size_t)n * 64 + o) + sv[e] * INVU + bo;
    }
  }

  // ---- u1 vector + residual ----
  {
    const int o = tid & 63;
    ull accA[4] = {0, 0, 0, 0}, accB[4] = {0, 0, 0, 0};
    if (tid < 64) {
      gemmK2<64, 64, 3 * TE>(Wvvu, o, &hvaT[0][0][0], &hvaT[0][1][0], accA, accB);
    } else {
      gemmK<64, 64, 3 * TE>(Wvvu, o, &hvaT[0][2][0], accA);
      gemmK<64, 64, TE>(Wsvu, o, &hs_rT[0][0], accB);
      float pf[8]; upk8(accB, pf);
#pragma unroll
      for (int e = 0; e < TE; e++) pT[o][e] = pf[e];
    }
    __syncthreads();
    float qa[8], qb[8];
    upk8(accA, qa); upk8(accB, qb);
    if (tid < 64) {
#pragma unroll
      for (int e = 0; e < TE; e++) {
        int n = n0 + e;
        if (n >= N) continue;
        float p = pT[o][e];
        out[(size_t)n * 256 + 64 + o * 3 + 0] =
            __ldg(node_v + (size_t)n * 192 + o * 3 + 0) + (qa[e] + p * avx[0][e]) * INVU;
        out[(size_t)n * 256 + 64 + o * 3 + 1] =
            __ldg(node_v + (size_t)n * 192 + o * 3 + 1) + (qb[e] + p * avx[1][e]) * INVU;
      }
    } else {
#pragma unroll
      for (int e = 0; e < TE; e++) {
        int n = n0 + e;
        if (n >= N) continue;
        out[(size_t)n * 256 + 64 + o * 3 + 2] =
            __ldg(node_v + (size_t)n * 192 + o * 3 + 2) + (qa[e] + qb[e] * avx[2][e]) * INVU;
      }
    }
  }
}

extern "C" void kernel_launch(void* const* d_in, const int* in_sizes, int n_in,
                              void* d_out, int out_size) {
  const float* node_s = (const float*)d_in[0];
  const float* node_v = (const float*)d_in[1];
  const float* nas    = (const float*)d_in[2];
  const float* nav    = (const float*)d_in[3];
  const float* eas    = (const float*)d_in[4];
  const float* eav    = (const float*)d_in[5];
  const float* add_f  = (const float*)d_in[6];
  const float* m1Wss  = (const float*)d_in[7];
  const float* m1Wvs  = (const float*)d_in[8];
  const float* m1Wsv  = (const float*)d_in[9];
  const float* m1Wvv  = (const float*)d_in[10];
  const float* m1b    = (const float*)d_in[11];
  const float* m2Wss  = (const float*)d_in[12];
  const float* m2Wvs  = (const float*)d_in[13];
  const float* m2Wsv  = (const float*)d_in[14];
  const float* m2Wvv  = (const float*)d_in[15];
  const float* m2b    = (const float*)d_in[16];
  const float* u0Wss  = (const float*)d_in[17];
  const float* u0Wvs  = (const float*)d_in[18];
  const float* u0Wsv  = (const float*)d_in[19];
  const float* u0Wvv  = (const float*)d_in[20];
  const float* u0b    = (const float*)d_in[21];
  const float* u1Wss  = (const float*)d_in[22];
  const float* u1Wvs  = (const float*)d_in[23];
  const float* u1Wsv  = (const float*)d_in[24];
  const float* u1Wvv  = (const float*)d_in[25];
  const float* u1b    = (const float*)d_in[26];
  const int* senders   = (const int*)d_in[27];
  const int* receivers = (const int*)d_in[28];

  int E = in_sizes[27];
  int N = in_sizes[0] / 64;

  zero_kernel<<<512, 256>>>(N);
  edge_kernel<<<(E + TE - 1) / TE, 128>>>(
      node_s, node_v, eas, eav, add_f,
      m1Wss, m1Wvs, m1Wsv, m1Wvv, m1b,
      m2Wss, m2Wvs, m2Wsv, m2Wvv, m2b,
      senders, receivers, E);
  node_kernel<<<(N + TE - 1) / TE, 128>>>(
      node_s, node_v, nas, nav,
      u0Wss, u0Wvs, u0Wsv, u0Wvv, u0b,
      u1Wss, u1Wvs, u1Wsv, u1Wvv, u1b,
      (float*)d_out, N);
}